// round 6
// baseline (speedup 1.0000x reference)
#include <cuda_runtime.h>
#include <cuda_bf16.h>
#include <cstdint>

#define Bq 256      // queries
#define Dk 768      // feature dim
#define Nn 131072   // database rows
#define Lo 512      // output row length

#define MARGIN 0.2f
#define CAND_CAP 65536

// smem: per buffer, q tile 128x72 bf16 (18432 B) + db tile 128x72 bf16 (18432 B)
#define F_QH   0
#define F_DH   18432
#define F_BUF  36864
#define F_INVN 73728
#define SMEM_TOTAL (F_INVN + 512 + 32)

__device__ __nv_bfloat16 g_qh[Bq * Dk];
__device__ float g_invn[Nn];
__device__ unsigned g_best[Bq];                 // sortable-float running max
__device__ unsigned long long g_best2[Bq];      // exact argmax keys
__device__ int g_cand_count;
__device__ unsigned g_cand[CAND_CAP];           // (q << 17) | n

// ---------------- helpers ----------------
__device__ __forceinline__ uint32_t smem_u32(const void* p) {
    uint32_t a;
    asm("{ .reg .u64 t; cvta.to.shared.u64 t, %1; cvt.u32.u64 %0, t; }"
        : "=r"(a) : "l"(p));
    return a;
}
__device__ __forceinline__ unsigned sortable32(float v) {
    unsigned u = __float_as_uint(v);
    return (u & 0x80000000u) ? ~u : (u | 0x80000000u);
}
__device__ __forceinline__ float unsortable32(unsigned s) {
    unsigned u = (s & 0x80000000u) ? (s & 0x7fffffffu) : ~s;
    return __uint_as_float(u);
}
__device__ __forceinline__ unsigned long long pack_key(float v, unsigned idx) {
    return ((unsigned long long)sortable32(v) << 32) | (unsigned)(~idx);
}
__device__ __forceinline__ uint32_t b2u(__nv_bfloat162 h) {
    return *reinterpret_cast<uint32_t*>(&h);
}
__device__ __forceinline__ void cp_async16(uint32_t dst, const void* src) {
    asm volatile("cp.async.ca.shared.global [%0], [%1], 16;"
                 :: "r"(dst), "l"(src) : "memory");
}
__device__ __forceinline__ void cp_commit() {
    asm volatile("cp.async.commit_group;" ::: "memory");
}
__device__ __forceinline__ void cp_wait_all() {
    asm volatile("cp.async.wait_group 0;" ::: "memory");
}
__device__ __forceinline__ void ldsm_x4(uint32_t* r, uint32_t a) {
    asm volatile("ldmatrix.sync.aligned.m8n8.x4.shared.b16 {%0,%1,%2,%3}, [%4];"
                 : "=r"(r[0]), "=r"(r[1]), "=r"(r[2]), "=r"(r[3]) : "r"(a));
}
__device__ __forceinline__ void mma16816(float* d, const uint32_t* a, const uint32_t* b) {
    asm volatile(
        "mma.sync.aligned.m16n8k16.row.col.f32.bf16.bf16.f32 "
        "{%0,%1,%2,%3},{%4,%5,%6,%7},{%8,%9},{%0,%1,%2,%3};"
        : "+f"(d[0]), "+f"(d[1]), "+f"(d[2]), "+f"(d[3])
        : "r"(a[0]), "r"(a[1]), "r"(a[2]), "r"(a[3]), "r"(b[0]), "r"(b[1]));
}

// ---------------- convert queries + init state ----------------
__global__ void convert_init_kernel(const float* __restrict__ x) {
    int i = blockIdx.x * 256 + threadIdx.x;
    g_qh[i] = __float2bfloat16(x[i]);
    if (blockIdx.x == 0) {
        g_best[threadIdx.x] = 0u;
        g_best2[threadIdx.x] = 0ull;
        if (threadIdx.x == 0) g_cand_count = 0;
    }
}

// ---------------- pass 1: bf16 GEMM + running-max candidate emission ----------------
// grid 2048: CTA = (n-tile 0..1023) x (q-half 0..1); 128q x 128n per CTA.
__global__ void __launch_bounds__(256, 2) sim_kernel(const float* __restrict__ db) {
    extern __shared__ char smem[];
    const uint32_t sb32 = smem_u32(smem);
    const int tid  = threadIdx.x;
    const int lane = tid & 31;
    const int w    = tid >> 5;
    const int q0   = (blockIdx.x & 1) * 128;
    const int n0   = (blockIdx.x >> 1) * 128;
    const int qb   = (w & 3) * 32;     // 32 queries per warp
    const int nb   = (w >> 2) * 64;    // 64 db rows per warp
    float* s_invn  = (float*)(smem + F_INVN);

    const int row  = tid >> 1;         // 0..127
    const int half = tid & 1;

    float acc[2][8][4];
#pragma unroll
    for (int a = 0; a < 2; a++)
#pragma unroll
        for (int b = 0; b < 8; b++)
#pragma unroll
            for (int r = 0; r < 4; r++) acc[a][b][r] = 0.f;
    float ps = 0.f;

#pragma unroll 1
    for (int c = 0; c < 12; c++) {
        const int bufo = (c & 1) * F_BUF;
        const int k0 = c * 64;
        // ---- q tile via cp.async (no conversion needed) ----
        {
            const __nv_bfloat16* qsrc = g_qh + (size_t)(q0 + row) * Dk + k0 + half * 32;
            uint32_t qdst = sb32 + bufo + F_QH + row * 144 + half * 64;
#pragma unroll
            for (int i = 0; i < 4; i++) cp_async16(qdst + i * 16, qsrc + i * 8);
            cp_commit();
        }
        // ---- db tile: fp32 -> bf16 convert, fuse norms ----
        {
            const float4* dsrc = (const float4*)(db + (size_t)(n0 + row) * Dk + k0 + half * 32);
            char* ph = smem + bufo + F_DH + row * 144 + half * 64;
#pragma unroll
            for (int i = 0; i < 8; i++) {
                float4 f = dsrc[i];
                ps = fmaf(f.x, f.x, fmaf(f.y, f.y, fmaf(f.z, f.z, fmaf(f.w, f.w, ps))));
                __nv_bfloat162 h01 = __floats2bfloat162_rn(f.x, f.y);
                __nv_bfloat162 h23 = __floats2bfloat162_rn(f.z, f.w);
                *(uint2*)(ph + i * 8) = make_uint2(b2u(h01), b2u(h23));
            }
        }
        cp_wait_all();
        __syncthreads();

        const uint32_t sqh = sb32 + bufo + F_QH;
        const uint32_t sdh = sb32 + bufo + F_DH;
#pragma unroll
        for (int ks = 0; ks < 4; ks++) {
            uint32_t aH[2][4];
#pragma unroll
            for (int mi = 0; mi < 2; mi++) {
                uint32_t ao = (uint32_t)((qb + mi * 16 + (lane & 15)) * 144 +
                                         ks * 32 + (lane >> 4) * 16);
                ldsm_x4(aH[mi], sqh + ao);
            }
#pragma unroll
            for (int nip = 0; nip < 4; nip++) {
                uint32_t bo = (uint32_t)((nb + nip * 16 + (lane & 7) +
                                          ((lane >> 4) & 1) * 8) * 144 +
                                         ks * 32 + ((lane >> 3) & 1) * 16);
                uint32_t bh[4];
                ldsm_x4(bh, sdh + bo);
#pragma unroll
                for (int mi = 0; mi < 2; mi++)
#pragma unroll
                    for (int s = 0; s < 2; s++)
                        mma16816(acc[mi][nip * 2 + s], aH[mi], &bh[2 * s]);
            }
        }
        // next iter writes the other buffer; buffer c&1 reused at c+2 after that sync
        __syncthreads();
    }

    // ---- inverse norms ----
    {
        float s = ps + __shfl_xor_sync(0xffffffffu, ps, 1);
        if (!half) {
            float r = 1.0f / fmaxf(sqrtf(s), 1e-8f);
            s_invn[row] = r;
            g_invn[n0 + row] = r;   // duplicate write across q-halves, same value
        }
    }
    __syncthreads();

    // ---- scale, per-q max, running global max, emit candidates ----
#pragma unroll
    for (int mi = 0; mi < 2; mi++)
#pragma unroll
        for (int g8 = 0; g8 < 2; g8++) {
            const int q = q0 + qb + mi * 16 + g8 * 8 + (lane >> 2);
            float m = -1e30f;
#pragma unroll
            for (int ni = 0; ni < 8; ni++)
#pragma unroll
                for (int s = 0; s < 2; s++) {
                    int nl = nb + ni * 8 + (lane & 3) * 2 + s;
                    float v = acc[mi][ni][g8 * 2 + s] * s_invn[nl];
                    acc[mi][ni][g8 * 2 + s] = v;
                    m = fmaxf(m, v);
                }
            m = fmaxf(m, __shfl_xor_sync(0xffffffffu, m, 1));
            m = fmaxf(m, __shfl_xor_sync(0xffffffffu, m, 2));
            unsigned cur;
            if ((lane & 3) == 0) {
                unsigned old = atomicMax(&g_best[q], sortable32(m));
                cur = max(old, sortable32(m));
            }
            cur = __shfl_sync(0xffffffffu, cur, lane & 28);
            float thr = unsortable32(cur) - MARGIN;
#pragma unroll
            for (int ni = 0; ni < 8; ni++)
#pragma unroll
                for (int s = 0; s < 2; s++) {
                    float v = acc[mi][ni][g8 * 2 + s];
                    if (v >= thr) {
                        int n = n0 + nb + ni * 8 + (lane & 3) * 2 + s;
                        int slot = atomicAdd(&g_cand_count, 1);
                        if (slot < CAND_CAP)
                            g_cand[slot] = ((unsigned)q << 17) | (unsigned)n;
                    }
                }
        }
}

// ---------------- pass 2: exact fp32 rescore of candidates ----------------
__global__ void __launch_bounds__(128) rescore_kernel(const float* __restrict__ x,
                                                      const float* __restrict__ db) {
    __shared__ float s_part[4];
    const int tid = threadIdx.x;
    int cnt = g_cand_count;
    if (cnt > CAND_CAP) cnt = CAND_CAP;

    for (int i = blockIdx.x; i < cnt; i += gridDim.x) {
        unsigned p = g_cand[i];
        unsigned q = p >> 17;
        unsigned n = p & 0x1FFFFu;
        const float* xq = x + (size_t)q * Dk;
        const float* dn = db + (size_t)n * Dk;
        float s = 0.f;
#pragma unroll
        for (int j = 0; j < 6; j++)
            s = fmaf(xq[tid + 128 * j], dn[tid + 128 * j], s);
#pragma unroll
        for (int m = 16; m; m >>= 1) s += __shfl_xor_sync(0xffffffffu, s, m);
        if ((tid & 31) == 0) s_part[tid >> 5] = s;
        __syncthreads();
        if (tid == 0) {
            float v = (s_part[0] + s_part[1] + s_part[2] + s_part[3]) * g_invn[n];
            atomicMax(&g_best2[q], pack_key(v, n));
        }
        __syncthreads();
    }
}

// ---------------- gather ----------------
__global__ void gather_kernel(const float* __restrict__ y, float* __restrict__ out) {
    const int b = blockIdx.x;
    unsigned idx = ~((unsigned)(g_best2[b] & 0xffffffffull));
    const float4* src = (const float4*)(y + (size_t)idx * Lo);
    float4* dst = (float4*)(out + (size_t)b * Lo);
    dst[threadIdx.x] = src[threadIdx.x];
}

extern "C" void kernel_launch(void* const* d_in, const int* in_sizes, int n_in,
                              void* d_out, int out_size) {
    const float* imu = (const float*)d_in[0];
    const float* dbx = (const float*)d_in[1];
    const float* dby = (const float*)d_in[2];
    float* out = (float*)d_out;

    cudaFuncSetAttribute(sim_kernel, cudaFuncAttributeMaxDynamicSharedMemorySize,
                         SMEM_TOTAL);

    convert_init_kernel<<<Dk, 256>>>(imu);
    sim_kernel<<<2048, 256, SMEM_TOTAL>>>(dbx);
    rescore_kernel<<<1024, 128>>>(imu, dbx);
    gather_kernel<<<Bq, Lo / 4>>>(dby, out);
}